// round 16
// baseline (speedup 1.0000x reference)
#include <cuda_runtime.h>
#include <cuda_fp16.h>
#include <mma.h>
#include <cstdint>

using namespace nvcuda;

#define NN 100000
#define EE 1600000
#define FF 64
#define CC 10
#define LL 4
#define BB 128
#define NTILE 782                   // row tiles of 128
#define LDH 72                      // fp16 smem leading dim (elements)
#define LDC 72                      // fp32 C leading dim
#define WLAYER (4 * 64 * LDH)       // halves per layer in pre-split image (18432)

// ---- scratch (__device__ globals; no allocs allowed) ----------------------
__device__ __half d_hX[(size_t)NN * FF];  // fp16 x
__device__ __half d_hA[(size_t)NN * FF];  // ping
__device__ __half d_hB[(size_t)NN * FF];  // pong
__device__ __half d_wsp[LL * WLAYER];     // pre-split weights (smem image)
__device__ int d_nbr[EE];
__device__ int d_deg[NN];
__device__ int d_rowptr[NN + 1];
__device__ int d_cursor[NN];
__device__ int d_batch[NN];
__device__ int d_flags[2];

__device__ __forceinline__ int load_idx(const void* p, long long i, int is32) {
    return is32 ? ((const int*)p)[i] : (int)((const long long*)p)[i];
}
__device__ __forceinline__ void fp16_split(float v, __half& hi, __half& lo) {
    hi = __float2half_rn(v);
    lo = __float2half_rn(v - __half2float(hi));
}

// ============================================================================
// preprocessing
// ============================================================================
// detect + zero deg + zero d_out; grid = 400 x 256
__global__ void detect_kernel(const unsigned* __restrict__ ei,
                              const unsigned* __restrict__ bt,
                              int* __restrict__ flags,
                              int* __restrict__ deg,
                              float* __restrict__ outbuf, int out_size) {
    int gid = blockIdx.x * 256 + threadIdx.x;
    if (blockIdx.x == 0) {
        if (threadIdx.x == 0) { flags[0] = 0; flags[1] = 0; }
        __syncthreads();
        int t = threadIdx.x;
        unsigned a = ei[2 * (t * 6000) + 1];
        if (a != 0u) atomicOr(&flags[0], 1);
        int i = NN / 4 + t * 97;
        unsigned b = bt[2 * i + 1];
        if (b != 0u) atomicOr(&flags[1], 1);
    }
    if (gid < NN) deg[gid] = 0;
    if (gid < out_size) outbuf[gid] = 0.f;
}

// pre-split all layers' weights into smem-image layout (transposed, hi/lo)
__global__ void k_wprep(const float* __restrict__ W1s, const float* __restrict__ W2s) {
    int gid = blockIdx.x * 256 + threadIdx.x;
    if (gid >= LL * 4096) return;
    int l = gid >> 12, i = gid & 4095;
    int k = i >> 6, n = i & 63;
    __half h1, l1, h2, l2;
    fp16_split(W1s[l * 4096 + i], h1, l1);
    fp16_split(W2s[l * 4096 + i], h2, l2);
    __half* base = d_wsp + l * WLAYER;
    base[0 * 4608 + n * LDH + k] = h1;
    base[1 * 4608 + n * LDH + k] = l1;
    base[2 * 4608 + n * LDH + k] = h2;
    base[3 * 4608 + n * LDH + k] = l2;
}

// fused: degree histogram + batch convert + x->fp16 (grid covers EE = NN*16)
__global__ void k_prep1(const void* __restrict__ ei, const void* __restrict__ bt,
                        const float* __restrict__ x,
                        int* __restrict__ deg, int* __restrict__ batch,
                        __half* __restrict__ hx, const int* __restrict__ flags) {
    int gid = blockIdx.x * 256 + threadIdx.x;
    int is32 = flags[0];
    if (gid < EE) {
        int d = load_idx(ei, (long long)EE + gid, is32);
        if ((unsigned)d < NN) atomicAdd(&deg[d], 1);
    }
    if (gid < NN * 16) {
        float4 v = ((const float4*)x)[gid];
        ((__half2*)hx)[2 * gid]     = __floats2half2_rn(v.x, v.y);
        ((__half2*)hx)[2 * gid + 1] = __floats2half2_rn(v.z, v.w);
    }
    if (gid < NN)
        batch[gid] = flags[1] ? ((const int*)bt)[gid] : (int)((const long long*)bt)[gid];
}

// single-block exclusive scan: deg -> rowptr, cursor  (1024 thr x 100 elems)
#define EPT 100
__global__ void __launch_bounds__(1024) k_scan(const int* __restrict__ deg,
                                               int* __restrict__ rowptr,
                                               int* __restrict__ cursor) {
    __shared__ int sh[1024];
    int t = threadIdx.x;
    int base = t * EPT;
    // pass 1: local sum
    int s = 0;
#pragma unroll 4
    for (int j = 0; j < EPT; j++) {
        int i = base + j;
        if (i < NN) s += deg[i];
    }
    sh[t] = s;
    __syncthreads();
    // block scan (inclusive)
    for (int d = 1; d < 1024; d <<= 1) {
        int add = (t >= d) ? sh[t - d] : 0;
        __syncthreads();
        sh[t] += add;
        __syncthreads();
    }
    int running = sh[t] - s;   // exclusive base
    // pass 2: write prefix
#pragma unroll 4
    for (int j = 0; j < EPT; j++) {
        int i = base + j;
        if (i < NN) {
            int v = deg[i];
            rowptr[i] = running;
            cursor[i] = running;
            running += v;
        }
    }
    if (t == 1023) rowptr[NN] = EE;
}

__global__ void k_scatter(const void* __restrict__ ei,
                          int* __restrict__ cursor, int* __restrict__ nbr,
                          const int* __restrict__ flags) {
    int e = blockIdx.x * blockDim.x + threadIdx.x;
    if (e >= EE) return;
    int is32 = flags[0];
    int s = load_idx(ei, e, is32);
    int d = load_idx(ei, (long long)EE + e, is32);
    if ((unsigned)d >= NN || (unsigned)s >= NN) return;
    int p = atomicAdd(&cursor[d], 1);
    nbr[p] = s;
}

// ============================================================================
// fused GIN layer: subwarp fp16 gather + 2-term fp16 wmma MLP, 54KB smem
// block = 256 threads (8 warps), tile = 128 rows, 4 blocks/SM
// weights staged via plain 36KB copy from pre-split d_wsp
// ============================================================================
__device__ __forceinline__ float fast_sigmoid(float x) {
    return __fdividef(1.0f, 1.0f + __expf(-x));
}
__device__ __forceinline__ void acc8(float* a, uint4 u) {
    float2 v0 = __half22float2(*(const __half2*)&u.x);
    float2 v1 = __half22float2(*(const __half2*)&u.y);
    float2 v2 = __half22float2(*(const __half2*)&u.z);
    float2 v3 = __half22float2(*(const __half2*)&u.w);
    a[0] += v0.x; a[1] += v0.y; a[2] += v1.x; a[3] += v1.y;
    a[4] += v2.x; a[5] += v2.y; a[6] += v3.x; a[7] += v3.y;
}

// smem layout (bytes):
//   [0, 18432)     A (fp16, 128*LDH)      -- C (fp32, 36864B) aliases A+W1hi+W1lo
//   [18432, 27648) W1hi
//   [27648, 36864) W1lo
//   [36864, 46080) W2hi   -- pool bins (2048B) alias W2hi after GEMM2
//   [46080, 55296) W2lo
#define SM_A    0
#define SM_W1HI 18432
#define SM_BINS 36864
#define SMEM_BYTES 55296   // 54KB -> 4 blocks/SM

__device__ __forceinline__ void gemm_acc_2xfp16(
    const __half* A, const __half* Whi, const __half* Wlo,
    wmma::fragment<wmma::accumulator, 16, 16, 16, float>* acc, int warp) {
#pragma unroll
    for (int nt = 0; nt < 4; nt++) wmma::fill_fragment(acc[nt], 0.0f);
    const __half* arow = A + (warp * 16) * LDH;
#pragma unroll
    for (int k = 0; k < 64; k += 16) {
        wmma::fragment<wmma::matrix_a, 16, 16, 16, __half, wmma::row_major> aF;
        wmma::load_matrix_sync(aF, arow + k, LDH);
#pragma unroll
        for (int nt = 0; nt < 4; nt++) {
            wmma::fragment<wmma::matrix_b, 16, 16, 16, __half, wmma::col_major> bHi, bLo;
            wmma::load_matrix_sync(bHi, Whi + (nt * 16) * LDH + k, LDH);
            wmma::load_matrix_sync(bLo, Wlo + (nt * 16) * LDH + k, LDH);
            wmma::mma_sync(acc[nt], aF, bHi, acc[nt]);
            wmma::mma_sync(acc[nt], aF, bLo, acc[nt]);
        }
    }
}

__global__ void __launch_bounds__(256, 4) layer_kernel(
    const __half* __restrict__ hin, __half* __restrict__ hout,
    const __half* __restrict__ wsp,           // pre-split weights for this layer
    const int* __restrict__ rowptr, const int* __restrict__ nbr,
    const int* __restrict__ batch, float* __restrict__ xr, int do_pool) {
    extern __shared__ char smb[];
    __half* A = (__half*)(smb + SM_A);
    __half* W1hi = (__half*)(smb + SM_W1HI);
    __half* W1lo = W1hi + 4608;
    __half* W2hi = W1hi + 2 * 4608;
    __half* W2lo = W1hi + 3 * 4608;
    float* C = (float*)(smb + SM_A);   // aliases A + W1hi + W1lo

    int tid = threadIdx.x;
    int warp = tid >> 5;
    int lane = tid & 31;
    int row0 = blockIdx.x * 128;

    // stage weights: plain 36KB uint4 copy from pre-split image
    {
        const uint4* src = (const uint4*)wsp;
        uint4* dst = (uint4*)(smb + SM_W1HI);
#pragma unroll
        for (int i = tid; i < WLAYER * 2 / 16; i += 256) dst[i] = src[i];
    }

    // subwarp gather: 8 lanes/row (uint4), 4 rows concurrent per warp
    {
        int sw = lane >> 3;
        int sl = lane & 7;
        const __half* hin_sl = hin + sl * 8;
#pragma unroll
        for (int rr = 0; rr < 16; rr += 4) {
            int r = warp * 16 + rr + sw;
            int g = row0 + r;
            float a[8] = {0.f, 0.f, 0.f, 0.f, 0.f, 0.f, 0.f, 0.f};
            if (g < NN) {
                acc8(a, *(const uint4*)(hin_sl + (size_t)g * FF));
                int beg = rowptr[g], end = rowptr[g + 1];
                for (int j = beg; j < end; j++) {
                    int s = __ldg(&nbr[j]);
                    acc8(a, *(const uint4*)(hin_sl + (size_t)s * FF));
                }
            }
            int cb = sl * 8;
#pragma unroll
            for (int q = 0; q < 4; q++)
                *(__half2*)(A + r * LDH + cb + 2 * q) = __floats2half2_rn(a[2 * q], a[2 * q + 1]);
        }
    }
    __syncthreads();

    wmma::fragment<wmma::accumulator, 16, 16, 16, float> acc[4];

    // GEMM 1 (acc in registers; A/W1 still live in smem)
    gemm_acc_2xfp16(A, W1hi, W1lo, acc, warp);
    __syncthreads();   // ALL warps done reading A/W1 before C (alias) is written
#pragma unroll
    for (int nt = 0; nt < 4; nt++)
        wmma::store_matrix_sync(C + (warp * 16) * LDC + nt * 16, acc[nt], LDC, wmma::mem_row_major);
    __syncthreads();

    // epilogue 1: C -> registers, barrier, sigmoid -> A (alias of C)
    {
        float2 v[16];
#pragma unroll
        for (int t = 0; t < 16; t++) {
            int i = tid + t * 256;
            int r = i >> 5, c2 = (i & 31) * 2;
            v[t] = *(const float2*)(C + r * LDC + c2);
        }
        __syncthreads();
#pragma unroll
        for (int t = 0; t < 16; t++) {
            int i = tid + t * 256;
            int r = i >> 5, c2 = (i & 31) * 2;
            *(__half2*)(A + r * LDH + c2) =
                __floats2half2_rn(fast_sigmoid(v[t].x), fast_sigmoid(v[t].y));
        }
    }
    __syncthreads();

    // GEMM 2 (W2 lives outside the C alias region)
    gemm_acc_2xfp16(A, W2hi, W2lo, acc, warp);
    __syncthreads();
#pragma unroll
    for (int nt = 0; nt < 4; nt++)
        wmma::store_matrix_sync(C + (warp * 16) * LDC + nt * 16, acc[nt], LDC, wmma::mem_row_major);
    __syncthreads();

    if (!do_pool) {
        // epilogue 2: sigmoid -> gmem as fp16
        int rl = tid >> 4;
        int c4 = (tid & 15) * 4;
#pragma unroll
        for (int rr = 0; rr < 128; rr += 16) {
            int r = row0 + rr + rl;
            if (r < NN) {
                const float* cs = C + (rr + rl) * LDC + c4;
                __half2 v0 = __floats2half2_rn(fast_sigmoid(cs[0]), fast_sigmoid(cs[1]));
                __half2 v1 = __floats2half2_rn(fast_sigmoid(cs[2]), fast_sigmoid(cs[3]));
                __half2* o = (__half2*)(hout + (size_t)r * FF + c4);
                o[0] = v0;
                o[1] = v1;
            }
        }
    } else {
        // fused pool: bins alias dead W2hi
        float* bins = (float*)(smb + SM_BINS);
        __shared__ int g0s;
        for (int i = tid; i < 512; i += 256) bins[i] = 0.f;
        if (tid == 0) g0s = batch[row0];
        __syncthreads();
        int g0 = g0s;
        int rl = tid >> 4;
        int c4 = (tid & 15) * 4;
#pragma unroll
        for (int rr = 0; rr < 128; rr += 16) {
            int r = row0 + rr + rl;
            if (r < NN) {
                const float* cs = C + (rr + rl) * LDC + c4;
                float v0 = fast_sigmoid(cs[0]);
                float v1 = fast_sigmoid(cs[1]);
                float v2 = fast_sigmoid(cs[2]);
                float v3 = fast_sigmoid(cs[3]);
                int b = batch[r];
                int g = b - g0;
                if ((unsigned)g < 8u) {
                    atomicAdd(&bins[g * 64 + c4 + 0], v0);
                    atomicAdd(&bins[g * 64 + c4 + 1], v1);
                    atomicAdd(&bins[g * 64 + c4 + 2], v2);
                    atomicAdd(&bins[g * 64 + c4 + 3], v3);
                } else if ((unsigned)b < BB) {
                    atomicAdd(&xr[b * 64 + c4 + 0], v0);
                    atomicAdd(&xr[b * 64 + c4 + 1], v1);
                    atomicAdd(&xr[b * 64 + c4 + 2], v2);
                    atomicAdd(&xr[b * 64 + c4 + 3], v3);
                }
            }
        }
        __syncthreads();
        for (int i = tid; i < 512; i += 256) {
            float v = bins[i];
            int g = g0 + (i >> 6);
            if (v != 0.f && (unsigned)g < BB) atomicAdd(&xr[g * 64 + (i & 63)], v);
        }
    }
}

// ============================================================================
// head: logits = xr @ fc_w^T + fc_b; out = log_softmax(logits)
// ============================================================================
__global__ void head_kernel(const float* __restrict__ xr, const float* __restrict__ fcw,
                            const float* __restrict__ fcb, float* __restrict__ out) {
    __shared__ float w[CC * FF];
    __shared__ float b[CC];
    for (int i = threadIdx.x; i < CC * FF; i += blockDim.x) w[i] = fcw[i];
    if (threadIdx.x < CC) b[threadIdx.x] = fcb[threadIdx.x];
    __syncthreads();
    int r = threadIdx.x;
    if (r < BB) {
        float lg[CC];
        float m = -1e30f;
        const float* row = xr + r * FF;
#pragma unroll
        for (int j = 0; j < CC; j++) {
            float a = b[j];
#pragma unroll
            for (int k = 0; k < FF; k++) a = fmaf(row[k], w[j * FF + k], a);
            lg[j] = a;
            m = fmaxf(m, a);
        }
        float s = 0.f;
#pragma unroll
        for (int j = 0; j < CC; j++) s += expf(lg[j] - m);
        float lse = m + logf(s);
#pragma unroll
        for (int j = 0; j < CC; j++) out[r * CC + j] = lg[j] - lse;
    }
}

// ============================================================================
extern "C" void kernel_launch(void* const* d_in, const int* in_sizes, int n_in,
                              void* d_out, int out_size) {
    const float* x = (const float*)d_in[0];
    const void* ei = d_in[1];
    const void* batch = d_in[2];
    const float* W1s = (const float*)d_in[3];
    const float* W2s = (const float*)d_in[4];
    const float* fcw = (const float*)d_in[5];
    const float* fcb = (const float*)d_in[6];
    float* out = (float*)d_out;

    __half *hX, *hA, *hB, *wsp;
    int *nbr, *deg, *rowptr, *cursor, *bt, *flags;
    cudaGetSymbolAddress((void**)&hX, d_hX);
    cudaGetSymbolAddress((void**)&hA, d_hA);
    cudaGetSymbolAddress((void**)&hB, d_hB);
    cudaGetSymbolAddress((void**)&wsp, d_wsp);
    cudaGetSymbolAddress((void**)&nbr, d_nbr);
    cudaGetSymbolAddress((void**)&deg, d_deg);
    cudaGetSymbolAddress((void**)&rowptr, d_rowptr);
    cudaGetSymbolAddress((void**)&cursor, d_cursor);
    cudaGetSymbolAddress((void**)&bt, d_batch);
    cudaGetSymbolAddress((void**)&flags, d_flags);

    cudaFuncSetAttribute(layer_kernel, cudaFuncAttributeMaxDynamicSharedMemorySize, SMEM_BYTES);

    float* xr = out + BB * CC;

    // preprocessing (5 kernels)
    detect_kernel<<<400, 256>>>((const unsigned*)ei, (const unsigned*)batch, flags,
                                deg, out, out_size);
    k_wprep<<<(LL * 4096 + 255) / 256, 256>>>(W1s, W2s);
    k_prep1<<<(EE + 255) / 256, 256>>>(ei, batch, x, deg, bt, hX, flags);
    k_scan<<<1, 1024>>>(deg, rowptr, cursor);
    k_scatter<<<(EE + 255) / 256, 256>>>(ei, cursor, nbr, flags);

    // 4 fused layers; layer 4 also does global_add_pool into xr
    layer_kernel<<<NTILE, 256, SMEM_BYTES>>>(hX, hA, wsp + 0 * WLAYER, rowptr, nbr, bt, xr, 0);
    layer_kernel<<<NTILE, 256, SMEM_BYTES>>>(hA, hB, wsp + 1 * WLAYER, rowptr, nbr, bt, xr, 0);
    layer_kernel<<<NTILE, 256, SMEM_BYTES>>>(hB, hA, wsp + 2 * WLAYER, rowptr, nbr, bt, xr, 0);
    layer_kernel<<<NTILE, 256, SMEM_BYTES>>>(hA, hB, wsp + 3 * WLAYER, rowptr, nbr, bt, xr, 1);

    head_kernel<<<1, 128>>>(xr, fcw, fcb, out);
}

// round 17
// speedup vs baseline: 1.6632x; 1.6632x over previous
#include <cuda_runtime.h>
#include <cuda_fp16.h>
#include <mma.h>
#include <cstdint>

using namespace nvcuda;

#define NN 100000
#define EE 1600000
#define FF 64
#define CC 10
#define LL 4
#define BB 128
#define NB 782                      // ceil(NN/128)
#define NTILE 782                   // row tiles of 128
#define LDH 72                      // fp16 smem leading dim (elements)
#define LDC 72                      // fp32 C leading dim
#define WLAYER (4 * 64 * LDH)       // halves per layer in pre-split image (18432)

// ---- scratch (__device__ globals; no allocs allowed) ----------------------
__device__ __half d_hX[(size_t)NN * FF];  // fp16 x
__device__ __half d_hA[(size_t)NN * FF];  // ping
__device__ __half d_hB[(size_t)NN * FF];  // pong
__device__ __half d_wsp[LL * WLAYER];     // pre-split weights (smem image)
__device__ int d_nbr[EE];
__device__ int d_deg[NN];
__device__ int d_rowptr[NN + 1];
__device__ int d_cursor[NN];
__device__ int d_batch[NN];
__device__ int d_bsum[1024];
__device__ int d_boff[1024];
__device__ int d_flags[2];

__device__ __forceinline__ int load_idx(const void* p, long long i, int is32) {
    return is32 ? ((const int*)p)[i] : (int)((const long long*)p)[i];
}
__device__ __forceinline__ void fp16_split(float v, __half& hi, __half& lo) {
    hi = __float2half_rn(v);
    lo = __float2half_rn(v - __half2float(hi));
}

// ============================================================================
// preprocessing
// ============================================================================
// detect + zero deg + zero d_out; grid = 400 x 256
__global__ void detect_kernel(const unsigned* __restrict__ ei,
                              const unsigned* __restrict__ bt,
                              int* __restrict__ flags,
                              int* __restrict__ deg,
                              float* __restrict__ outbuf, int out_size) {
    int gid = blockIdx.x * 256 + threadIdx.x;
    if (blockIdx.x == 0) {
        if (threadIdx.x == 0) { flags[0] = 0; flags[1] = 0; }
        __syncthreads();
        int t = threadIdx.x;
        unsigned a = ei[2 * (t * 6000) + 1];
        if (a != 0u) atomicOr(&flags[0], 1);
        int i = NN / 4 + t * 97;
        unsigned b = bt[2 * i + 1];
        if (b != 0u) atomicOr(&flags[1], 1);
    }
    if (gid < NN) deg[gid] = 0;
    if (gid < out_size) outbuf[gid] = 0.f;
}

// pre-split all layers' weights into smem-image layout (transposed, hi/lo)
__global__ void k_wprep(const float* __restrict__ W1s, const float* __restrict__ W2s) {
    int gid = blockIdx.x * 256 + threadIdx.x;
    if (gid >= LL * 4096) return;
    int l = gid >> 12, i = gid & 4095;
    int k = i >> 6, n = i & 63;
    __half h1, l1, h2, l2;
    fp16_split(W1s[l * 4096 + i], h1, l1);
    fp16_split(W2s[l * 4096 + i], h2, l2);
    __half* base = d_wsp + l * WLAYER;
    base[0 * 4608 + n * LDH + k] = h1;
    base[1 * 4608 + n * LDH + k] = l1;
    base[2 * 4608 + n * LDH + k] = h2;
    base[3 * 4608 + n * LDH + k] = l2;
}

// fused: degree histogram + batch convert + x->fp16 (grid covers EE = NN*16)
__global__ void k_prep1(const void* __restrict__ ei, const void* __restrict__ bt,
                        const float* __restrict__ x,
                        int* __restrict__ deg, int* __restrict__ batch,
                        __half* __restrict__ hx, const int* __restrict__ flags) {
    int gid = blockIdx.x * 256 + threadIdx.x;
    int is32 = flags[0];
    if (gid < EE) {
        int d = load_idx(ei, (long long)EE + gid, is32);
        if ((unsigned)d < NN) atomicAdd(&deg[d], 1);
    }
    if (gid < NN * 16) {
        float4 v = ((const float4*)x)[gid];
        ((__half2*)hx)[2 * gid]     = __floats2half2_rn(v.x, v.y);
        ((__half2*)hx)[2 * gid + 1] = __floats2half2_rn(v.z, v.w);
    }
    if (gid < NN)
        batch[gid] = flags[1] ? ((const int*)bt)[gid] : (int)((const long long*)bt)[gid];
}

// scan trio (proven 13.7us): bsum -> bscan -> rowptr
__global__ void k_bsum(const int* __restrict__ deg, int* __restrict__ bsum) {
    __shared__ int sh[128];
    int i = blockIdx.x * 128 + threadIdx.x;
    int v = (i < NN) ? deg[i] : 0;
    sh[threadIdx.x] = v;
    __syncthreads();
    for (int s = 64; s > 0; s >>= 1) {
        if (threadIdx.x < s) sh[threadIdx.x] += sh[threadIdx.x + s];
        __syncthreads();
    }
    if (threadIdx.x == 0) bsum[blockIdx.x] = sh[0];
}

__global__ void k_bscan(const int* __restrict__ bsum, int* __restrict__ boff) {
    __shared__ int sh[1024];
    int t = threadIdx.x;
    int v = (t < NB) ? bsum[t] : 0;
    sh[t] = v;
    __syncthreads();
    for (int s = 1; s < 1024; s <<= 1) {
        int add = (t >= s) ? sh[t - s] : 0;
        __syncthreads();
        sh[t] += add;
        __syncthreads();
    }
    if (t < NB) boff[t] = sh[t] - v;
}

__global__ void k_rowptr(const int* __restrict__ deg, const int* __restrict__ boff,
                         int* __restrict__ rowptr, int* __restrict__ cursor) {
    __shared__ int sh[128];
    int i = blockIdx.x * 128 + threadIdx.x;
    int t = threadIdx.x;
    int v = (i < NN) ? deg[i] : 0;
    sh[t] = v;
    __syncthreads();
    for (int s = 1; s < 128; s <<= 1) {
        int add = (t >= s) ? sh[t - s] : 0;
        __syncthreads();
        sh[t] += add;
        __syncthreads();
    }
    if (i < NN) {
        int off = boff[blockIdx.x] + sh[t] - v;
        rowptr[i] = off;
        cursor[i] = off;
    }
    if (blockIdx.x == 0 && t == 0) rowptr[NN] = EE;
}

__global__ void k_scatter(const void* __restrict__ ei,
                          int* __restrict__ cursor, int* __restrict__ nbr,
                          const int* __restrict__ flags) {
    int e = blockIdx.x * blockDim.x + threadIdx.x;
    if (e >= EE) return;
    int is32 = flags[0];
    int s = load_idx(ei, e, is32);
    int d = load_idx(ei, (long long)EE + e, is32);
    if ((unsigned)d >= NN || (unsigned)s >= NN) return;
    int p = atomicAdd(&cursor[d], 1);
    nbr[p] = s;
}

// ============================================================================
// fused GIN layer: subwarp fp16 gather + 2-term fp16 wmma MLP, 54KB smem
// block = 256 threads (8 warps), tile = 128 rows, 4 blocks/SM
// weights staged via plain 36KB copy from pre-split d_wsp
// ============================================================================
__device__ __forceinline__ float fast_sigmoid(float x) {
    return __fdividef(1.0f, 1.0f + __expf(-x));
}
__device__ __forceinline__ void acc8(float* a, uint4 u) {
    float2 v0 = __half22float2(*(const __half2*)&u.x);
    float2 v1 = __half22float2(*(const __half2*)&u.y);
    float2 v2 = __half22float2(*(const __half2*)&u.z);
    float2 v3 = __half22float2(*(const __half2*)&u.w);
    a[0] += v0.x; a[1] += v0.y; a[2] += v1.x; a[3] += v1.y;
    a[4] += v2.x; a[5] += v2.y; a[6] += v3.x; a[7] += v3.y;
}

// smem layout (bytes):
//   [0, 18432)     A (fp16, 128*LDH)      -- C (fp32, 36864B) aliases A+W1hi+W1lo
//   [18432, 27648) W1hi
//   [27648, 36864) W1lo
//   [36864, 46080) W2hi   -- pool bins (2048B) alias W2hi after GEMM2
//   [46080, 55296) W2lo
#define SM_A    0
#define SM_W1HI 18432
#define SM_BINS 36864
#define SMEM_BYTES 55296   // 54KB -> 4 blocks/SM

__device__ __forceinline__ void gemm_acc_2xfp16(
    const __half* A, const __half* Whi, const __half* Wlo,
    wmma::fragment<wmma::accumulator, 16, 16, 16, float>* acc, int warp) {
#pragma unroll
    for (int nt = 0; nt < 4; nt++) wmma::fill_fragment(acc[nt], 0.0f);
    const __half* arow = A + (warp * 16) * LDH;
#pragma unroll
    for (int k = 0; k < 64; k += 16) {
        wmma::fragment<wmma::matrix_a, 16, 16, 16, __half, wmma::row_major> aF;
        wmma::load_matrix_sync(aF, arow + k, LDH);
#pragma unroll
        for (int nt = 0; nt < 4; nt++) {
            wmma::fragment<wmma::matrix_b, 16, 16, 16, __half, wmma::col_major> bHi, bLo;
            wmma::load_matrix_sync(bHi, Whi + (nt * 16) * LDH + k, LDH);
            wmma::load_matrix_sync(bLo, Wlo + (nt * 16) * LDH + k, LDH);
            wmma::mma_sync(acc[nt], aF, bHi, acc[nt]);
            wmma::mma_sync(acc[nt], aF, bLo, acc[nt]);
        }
    }
}

__global__ void __launch_bounds__(256, 4) layer_kernel(
    const __half* __restrict__ hin, __half* __restrict__ hout,
    const __half* __restrict__ wsp,           // pre-split weights for this layer
    const int* __restrict__ rowptr, const int* __restrict__ nbr,
    const int* __restrict__ batch, float* __restrict__ xr, int do_pool) {
    extern __shared__ char smb[];
    __half* A = (__half*)(smb + SM_A);
    __half* W1hi = (__half*)(smb + SM_W1HI);
    __half* W1lo = W1hi + 4608;
    __half* W2hi = W1hi + 2 * 4608;
    __half* W2lo = W1hi + 3 * 4608;
    float* C = (float*)(smb + SM_A);   // aliases A + W1hi + W1lo

    int tid = threadIdx.x;
    int warp = tid >> 5;
    int lane = tid & 31;
    int row0 = blockIdx.x * 128;

    // stage weights: plain 36KB uint4 copy from pre-split image
    {
        const uint4* src = (const uint4*)wsp;
        uint4* dst = (uint4*)(smb + SM_W1HI);
#pragma unroll
        for (int i = tid; i < WLAYER * 2 / 16; i += 256) dst[i] = src[i];
    }

    // subwarp gather: 8 lanes/row (uint4), 4 rows concurrent per warp
    {
        int sw = lane >> 3;
        int sl = lane & 7;
        const __half* hin_sl = hin + sl * 8;
#pragma unroll
        for (int rr = 0; rr < 16; rr += 4) {
            int r = warp * 16 + rr + sw;
            int g = row0 + r;
            float a[8] = {0.f, 0.f, 0.f, 0.f, 0.f, 0.f, 0.f, 0.f};
            if (g < NN) {
                acc8(a, *(const uint4*)(hin_sl + (size_t)g * FF));
                int beg = rowptr[g], end = rowptr[g + 1];
                for (int j = beg; j < end; j++) {
                    int s = __ldg(&nbr[j]);
                    acc8(a, *(const uint4*)(hin_sl + (size_t)s * FF));
                }
            }
            int cb = sl * 8;
#pragma unroll
            for (int q = 0; q < 4; q++)
                *(__half2*)(A + r * LDH + cb + 2 * q) = __floats2half2_rn(a[2 * q], a[2 * q + 1]);
        }
    }
    __syncthreads();

    wmma::fragment<wmma::accumulator, 16, 16, 16, float> acc[4];

    // GEMM 1 (acc in registers; A/W1 still live in smem)
    gemm_acc_2xfp16(A, W1hi, W1lo, acc, warp);
    __syncthreads();   // ALL warps done reading A/W1 before C (alias) is written
#pragma unroll
    for (int nt = 0; nt < 4; nt++)
        wmma::store_matrix_sync(C + (warp * 16) * LDC + nt * 16, acc[nt], LDC, wmma::mem_row_major);
    __syncthreads();

    // epilogue 1: C -> registers, barrier, sigmoid -> A (alias of C)
    {
        float2 v[16];
#pragma unroll
        for (int t = 0; t < 16; t++) {
            int i = tid + t * 256;
            int r = i >> 5, c2 = (i & 31) * 2;
            v[t] = *(const float2*)(C + r * LDC + c2);
        }
        __syncthreads();
#pragma unroll
        for (int t = 0; t < 16; t++) {
            int i = tid + t * 256;
            int r = i >> 5, c2 = (i & 31) * 2;
            *(__half2*)(A + r * LDH + c2) =
                __floats2half2_rn(fast_sigmoid(v[t].x), fast_sigmoid(v[t].y));
        }
    }
    __syncthreads();

    // GEMM 2 (W2 lives outside the C alias region)
    gemm_acc_2xfp16(A, W2hi, W2lo, acc, warp);
    __syncthreads();
#pragma unroll
    for (int nt = 0; nt < 4; nt++)
        wmma::store_matrix_sync(C + (warp * 16) * LDC + nt * 16, acc[nt], LDC, wmma::mem_row_major);
    __syncthreads();

    if (!do_pool) {
        // epilogue 2: sigmoid -> gmem as fp16
        int rl = tid >> 4;
        int c4 = (tid & 15) * 4;
#pragma unroll
        for (int rr = 0; rr < 128; rr += 16) {
            int r = row0 + rr + rl;
            if (r < NN) {
                const float* cs = C + (rr + rl) * LDC + c4;
                __half2 v0 = __floats2half2_rn(fast_sigmoid(cs[0]), fast_sigmoid(cs[1]));
                __half2 v1 = __floats2half2_rn(fast_sigmoid(cs[2]), fast_sigmoid(cs[3]));
                __half2* o = (__half2*)(hout + (size_t)r * FF + c4);
                o[0] = v0;
                o[1] = v1;
            }
        }
    } else {
        // fused pool: bins alias dead W2hi
        float* bins = (float*)(smb + SM_BINS);
        __shared__ int g0s;
        for (int i = tid; i < 512; i += 256) bins[i] = 0.f;
        if (tid == 0) g0s = batch[row0];
        __syncthreads();
        int g0 = g0s;
        int rl = tid >> 4;
        int c4 = (tid & 15) * 4;
#pragma unroll
        for (int rr = 0; rr < 128; rr += 16) {
            int r = row0 + rr + rl;
            if (r < NN) {
                const float* cs = C + (rr + rl) * LDC + c4;
                float v0 = fast_sigmoid(cs[0]);
                float v1 = fast_sigmoid(cs[1]);
                float v2 = fast_sigmoid(cs[2]);
                float v3 = fast_sigmoid(cs[3]);
                int b = batch[r];
                int g = b - g0;
                if ((unsigned)g < 8u) {
                    atomicAdd(&bins[g * 64 + c4 + 0], v0);
                    atomicAdd(&bins[g * 64 + c4 + 1], v1);
                    atomicAdd(&bins[g * 64 + c4 + 2], v2);
                    atomicAdd(&bins[g * 64 + c4 + 3], v3);
                } else if ((unsigned)b < BB) {
                    atomicAdd(&xr[b * 64 + c4 + 0], v0);
                    atomicAdd(&xr[b * 64 + c4 + 1], v1);
                    atomicAdd(&xr[b * 64 + c4 + 2], v2);
                    atomicAdd(&xr[b * 64 + c4 + 3], v3);
                }
            }
        }
        __syncthreads();
        for (int i = tid; i < 512; i += 256) {
            float v = bins[i];
            int g = g0 + (i >> 6);
            if (v != 0.f && (unsigned)g < BB) atomicAdd(&xr[g * 64 + (i & 63)], v);
        }
    }
}

// ============================================================================
// head: logits = xr @ fc_w^T + fc_b; out = log_softmax(logits)
// ============================================================================
__global__ void head_kernel(const float* __restrict__ xr, const float* __restrict__ fcw,
                            const float* __restrict__ fcb, float* __restrict__ out) {
    __shared__ float w[CC * FF];
    __shared__ float b[CC];
    for (int i = threadIdx.x; i < CC * FF; i += blockDim.x) w[i] = fcw[i];
    if (threadIdx.x < CC) b[threadIdx.x] = fcb[threadIdx.x];
    __syncthreads();
    int r = threadIdx.x;
    if (r < BB) {
        float lg[CC];
        float m = -1e30f;
        const float* row = xr + r * FF;
#pragma unroll
        for (int j = 0; j < CC; j++) {
            float a = b[j];
#pragma unroll
            for (int k = 0; k < FF; k++) a = fmaf(row[k], w[j * FF + k], a);
            lg[j] = a;
            m = fmaxf(m, a);
        }
        float s = 0.f;
#pragma unroll
        for (int j = 0; j < CC; j++) s += expf(lg[j] - m);
        float lse = m + logf(s);
#pragma unroll
        for (int j = 0; j < CC; j++) out[r * CC + j] = lg[j] - lse;
    }
}

// ============================================================================
extern "C" void kernel_launch(void* const* d_in, const int* in_sizes, int n_in,
                              void* d_out, int out_size) {
    const float* x = (const float*)d_in[0];
    const void* ei = d_in[1];
    const void* batch = d_in[2];
    const float* W1s = (const float*)d_in[3];
    const float* W2s = (const float*)d_in[4];
    const float* fcw = (const float*)d_in[5];
    const float* fcb = (const float*)d_in[6];
    float* out = (float*)d_out;

    __half *hX, *hA, *hB, *wsp;
    int *nbr, *deg, *rowptr, *cursor, *bt, *bsum, *boff, *flags;
    cudaGetSymbolAddress((void**)&hX, d_hX);
    cudaGetSymbolAddress((void**)&hA, d_hA);
    cudaGetSymbolAddress((void**)&hB, d_hB);
    cudaGetSymbolAddress((void**)&wsp, d_wsp);
    cudaGetSymbolAddress((void**)&nbr, d_nbr);
    cudaGetSymbolAddress((void**)&deg, d_deg);
    cudaGetSymbolAddress((void**)&rowptr, d_rowptr);
    cudaGetSymbolAddress((void**)&cursor, d_cursor);
    cudaGetSymbolAddress((void**)&bt, d_batch);
    cudaGetSymbolAddress((void**)&bsum, d_bsum);
    cudaGetSymbolAddress((void**)&boff, d_boff);
    cudaGetSymbolAddress((void**)&flags, d_flags);

    cudaFuncSetAttribute(layer_kernel, cudaFuncAttributeMaxDynamicSharedMemorySize, SMEM_BYTES);

    float* xr = out + BB * CC;

    // preprocessing (scan trio restored; wprep kept)
    detect_kernel<<<400, 256>>>((const unsigned*)ei, (const unsigned*)batch, flags,
                                deg, out, out_size);
    k_wprep<<<(LL * 4096 + 255) / 256, 256>>>(W1s, W2s);
    k_prep1<<<(EE + 255) / 256, 256>>>(ei, batch, x, deg, bt, hX, flags);
    k_bsum<<<NB, 128>>>(deg, bsum);
    k_bscan<<<1, 1024>>>(bsum, boff);
    k_rowptr<<<NB, 128>>>(deg, boff, rowptr, cursor);
    k_scatter<<<(EE + 255) / 256, 256>>>(ei, cursor, nbr, flags);

    // 4 fused layers; layer 4 also does global_add_pool into xr
    layer_kernel<<<NTILE, 256, SMEM_BYTES>>>(hX, hA, wsp + 0 * WLAYER, rowptr, nbr, bt, xr, 0);
    layer_kernel<<<NTILE, 256, SMEM_BYTES>>>(hA, hB, wsp + 1 * WLAYER, rowptr, nbr, bt, xr, 0);
    layer_kernel<<<NTILE, 256, SMEM_BYTES>>>(hB, hA, wsp + 2 * WLAYER, rowptr, nbr, bt, xr, 0);
    layer_kernel<<<NTILE, 256, SMEM_BYTES>>>(hA, hB, wsp + 3 * WLAYER, rowptr, nbr, bt, xr, 1);

    head_kernel<<<1, 128>>>(xr, fcw, fcb, out);
}